// round 16
// baseline (speedup 1.0000x reference)
#include <cuda_runtime.h>
#include <cuda_bf16.h>
#include <math_constants.h>
#include <cstdint>

#define NB 148
#define TM 64
#define DF 128
#define BATCH 16
#define NTHR 640

#define SM_WH 0
#define SM_WL 32768
#define SM_X  65536          // 2 buffers x (XH 16K + XL 16K)
#define SM_PH 131072
#define SM_PL 133376
#define SM_SPART 135680      // 2 x [8 nga][64 r][19] = 2 x 38912
#define SM_ANC 213504
#define SM_SC 221696
#define SM_MB 221760
#define SM_LB 221824
#define SM_FLG 221888
#define SMEM_TOTAL 221952
#define SM_FSH SM_SPART

typedef unsigned long long ull;

__device__ __forceinline__ uint32_t smem_u32(const void* p) {
    uint32_t a;
    asm("{ .reg .u64 t; cvta.to.shared.u64 t, %1; cvt.u32.u64 %0, t; }" : "=r"(a) : "l"(p));
    return a;
}
__device__ __forceinline__ uint32_t cvt_bf2(float lo, float hi) {
    uint32_t r; asm("cvt.rn.bf16x2.f32 %0, %1, %2;" : "=r"(r) : "f"(hi), "f"(lo)); return r;
}
__device__ __forceinline__ ull fadd2(ull a, ull b) {
    ull d; asm("add.rn.f32x2 %0, %1, %2;" : "=l"(d) : "l"(a), "l"(b)); return d;
}
__device__ __forceinline__ ull pack2(float a, float b) {
    ull d; asm("mov.b64 %0, {%1, %2};" : "=l"(d) : "f"(a), "f"(b)); return d;
}
__device__ __forceinline__ float2 unpk(ull v) {
    float2 r; asm("mov.b64 {%0, %1}, %2;" : "=f"(r.x), "=f"(r.y) : "l"(v)); return r;
}
__device__ __forceinline__ void ldsm4(uint32_t* d, uint32_t a) {
    asm volatile("ldmatrix.sync.aligned.m8n8.x4.shared.b16 {%0,%1,%2,%3}, [%4];"
        : "=r"(d[0]), "=r"(d[1]), "=r"(d[2]), "=r"(d[3]) : "r"(a));
}
__device__ __forceinline__ void ldsm4t(uint32_t* d, uint32_t a) {
    asm volatile("ldmatrix.sync.aligned.m8n8.x4.trans.shared.b16 {%0,%1,%2,%3}, [%4];"
        : "=r"(d[0]), "=r"(d[1]), "=r"(d[2]), "=r"(d[3]) : "r"(a));
}
__device__ __forceinline__ void mma16816(float* c, const uint32_t* a, uint32_t b0, uint32_t b1) {
    asm volatile("mma.sync.aligned.m16n8k16.row.col.f32.bf16.bf16.f32 "
        "{%0,%1,%2,%3}, {%4,%5,%6,%7}, {%8,%9}, {%0,%1,%2,%3};"
        : "+f"(c[0]), "+f"(c[1]), "+f"(c[2]), "+f"(c[3])
        : "r"(a[0]), "r"(a[1]), "r"(a[2]), "r"(a[3]), "r"(b0), "r"(b1));
}
__device__ __forceinline__ uint32_t swz(int row, int col, int AC) {
    uint32_t o = (uint32_t)(((row >> 3) + (col >> 6) * AC) * 1024 + (row & 7) * 128 + (col & 63) * 2);
    return o ^ ((o >> 3) & 0x70);
}
__device__ __forceinline__ float quadred4(float s0, float s1, float s2, float s3, int lane) {
    float u = (lane & 1) ? s0 : s1;
    u = __shfl_xor_sync(0xffffffffu, u, 1);
    float A = (lane & 1) ? (s1 + u) : (s0 + u);
    float v = (lane & 1) ? s2 : s3;
    v = __shfl_xor_sync(0xffffffffu, v, 1);
    float Bv = (lane & 1) ? (s3 + v) : (s2 + v);
    float w = (lane & 2) ? A : Bv;
    w = __shfl_xor_sync(0xffffffffu, w, 2);
    return ((lane & 2) ? Bv : A) + w;
}

__device__ uint32_t g_Wh[8192];
__device__ uint32_t g_Wl[8192];
__device__ float g_anchor[BATCH * 128];
__device__ float g_pm[NB * BATCH];
__device__ float g_pl[NB * BATCH];
__device__ float g_pv[NB * BATCH * DF];
__device__ int g_cnt = 0;

__global__ __launch_bounds__(512)
void prep_kernel(const float* __restrict__ xxa, const float* __restrict__ W1) {
    int blk = blockIdx.x;
    if (blk < 16) {
        int idx = blk * 512 + threadIdx.x;
        int o = idx >> 6, k0 = (idx & 63) * 2;
        float w0 = W1[o * 256 + 128 + k0], w1 = W1[o * 256 + 128 + k0 + 1];
        uint32_t h = cvt_bf2(w0, w1);
        float h0 = __uint_as_float(h << 16), h1 = __uint_as_float(h & 0xffff0000u);
        uint32_t sw = swz(o, k0, 16) >> 2;
        g_Wh[sw] = h;
        g_Wl[sw] = cvt_bf2(w0 - h0, w1 - h1);
    } else {
        int gw = (blk - 16) * 16 + (threadIdx.x >> 5);
        int lane = threadIdx.x & 31;
        int b = gw >> 7, o = gw & 127;
        float4 xa = *(const float4*)&xxa[b * 128 + lane * 4];
        float4 wv = *(const float4*)&W1[o * 256 + lane * 4];
        float s = xa.x * wv.x;
        s = fmaf(xa.y, wv.y, s); s = fmaf(xa.z, wv.z, s); s = fmaf(xa.w, wv.w, s);
#pragma unroll
        for (int off = 16; off; off >>= 1) s += __shfl_xor_sync(0xffffffffu, s, off);
        if (lane == 0) g_anchor[b * 128 + o] = s;
    }
}

#define LDST_X(mm, bo) {                                                    \
    _Pragma("unroll 4")                                                     \
    for (int jj = 0; jj < 16; jj++) {                                       \
        int idx = lw + 128 * jj;                                            \
        int r = idx >> 5, c4 = (idx & 31) * 4;                              \
        float4 v = *(const float4*)&X[(size_t)min((mm) + r, M - 1) * DF + c4]; \
        uint32_t h0 = cvt_bf2(v.x, v.y), h1 = cvt_bf2(v.z, v.w);            \
        float f0 = __uint_as_float(h0 << 16), f1 = __uint_as_float(h0 & 0xffff0000u); \
        float f2 = __uint_as_float(h1 << 16), f3 = __uint_as_float(h1 & 0xffff0000u); \
        uint32_t l0 = cvt_bf2(v.x - f0, v.y - f1);                          \
        uint32_t l1 = cvt_bf2(v.z - f2, v.w - f3);                          \
        uint32_t so = swz(r, c4, 8) + (bo);                                 \
        *(ull*)(smem + SM_X + so) = (ull)h0 | ((ull)h1 << 32);              \
        *(ull*)(smem + SM_X + 16384 + so) = (ull)l0 | ((ull)l1 << 32);      \
    } }

__global__ __launch_bounds__(NTHR, 1)
void main_kernel(const float* __restrict__ X, const float* __restrict__ W2,
                 float* __restrict__ out, int M, int nTiles) {
    extern __shared__ char smem[];
    const uint32_t smb = smem_u32(smem);
    float* spart = (float*)(smem + SM_SPART);
    float* anc   = (float*)(smem + SM_ANC);
    float* scsh  = (float*)(smem + SM_SC);
    float* mbp   = (float*)(smem + SM_MB);
    float* lbp   = (float*)(smem + SM_LB);

    const int tid = threadIdx.x, bxi = blockIdx.x;
    const int wid = tid >> 5, lane = tid & 31;

    {
        const float4* wh = (const float4*)g_Wh;
        const float4* wl = (const float4*)g_Wl;
        float4* dh = (float4*)(smem + SM_WH);
        float4* dl = (float4*)(smem + SM_WL);
        for (int i = tid; i < 2048; i += NTHR) { dh[i] = wh[i]; dl[i] = wl[i]; }
        for (int i = tid; i < BATCH * 128; i += NTHR) anc[i] = g_anchor[i];
        if (tid < 16) { mbp[tid] = -CUDART_INF_F; lbp[tid] = 0.f; }
    }

    if (wid < 16) {
        // ===================== COMPUTE WARPS =====================
        const int mga = wid >> 3, nga = wid & 7;
        const int lgrp = lane >> 3;
        const int aRow0 = mga * 32 + (lgrp & 1) * 8 + (lane & 7);
        const uint32_t aB0 = smb + SM_X + ((uint32_t)(aRow0 >> 3) << 10) + ((uint32_t)(aRow0 & 7) << 7);
        const uint32_t cxa = ((uint32_t)((lgrp >> 1) * 16)) ^ ((uint32_t)(aRow0 & 7) << 4);
        const int bRow = nga * 16 + (lgrp >> 1) * 8 + (lane & 7);
        const uint32_t bB = smb + SM_WH + ((uint32_t)(bRow >> 3) << 10) + ((uint32_t)(bRow & 7) << 7);
        const uint32_t cxb = ((uint32_t)((lgrp & 1) * 16)) ^ ((uint32_t)(bRow & 7) << 4);
        const int c0 = nga * 16 + (lane & 3) * 2;
        const float2 w2a = make_float2(0.5f * W2[c0], 0.5f * W2[c0 + 1]);
        const float2 w2b = make_float2(0.5f * W2[c0 + 8], 0.5f * W2[c0 + 9]);
        const int spW = nga * 1216 + (mga * 32 + (lane >> 2) + 8 * (lane & 3)) * 19;

        float linbreg;
        {
            float4 a4 = *(const float4*)&g_anchor[wid * 128 + lane * 4];
            float4 w4 = *(const float4*)&W2[lane * 4];
            float d = a4.x * w4.x;
            d = fmaf(a4.y, w4.y, d); d = fmaf(a4.z, w4.z, d); d = fmaf(a4.w, w4.w, d);
#pragma unroll
            for (int off = 16; off; off >>= 1) d += __shfl_xor_sync(0xffffffffu, d, off);
            linbreg = 0.5f * d;
        }
        __syncthreads();                 // initial X tiles stored by loaders

        int k = 0;
        for (int t = bxi; t < nTiles; t += NB, k++) {
            const uint32_t xb = (uint32_t)((k & 1) * 32768);
            float* sp = spart + (k & 1) * 9728;     // spart parity buffer

            // B: NP GEMM
            float acc[2][2][4];
#pragma unroll
            for (int mt = 0; mt < 2; mt++)
#pragma unroll
                for (int nt = 0; nt < 2; nt++)
#pragma unroll
                    for (int e = 0; e < 4; e++) acc[mt][nt][e] = 0.f;
#pragma unroll
            for (int ks = 0; ks < 8; ks++) {
                uint32_t kb = (uint32_t)((ks & 3) * 32);
                uint32_t aAddr = aB0 + xb + (uint32_t)((ks >> 2) * 8192)  + (kb ^ cxa);
                uint32_t bAddr = bB  + (uint32_t)((ks >> 2) * 16384) + (kb ^ cxb);
                uint32_t ah0[4], ah1[4], al0[4], al1[4], bh[4], bl[4];
                ldsm4(ah0, aAddr);
                ldsm4(ah1, aAddr + 2048);
                ldsm4(al0, aAddr + 16384);
                ldsm4(al1, aAddr + 18432);
                ldsm4(bh, bAddr);
                ldsm4(bl, bAddr + 32768);
#pragma unroll
                for (int mt = 0; mt < 2; mt++) {
                    const uint32_t* ah = mt ? ah1 : ah0;
                    const uint32_t* al = mt ? al1 : al0;
#pragma unroll
                    for (int nt = 0; nt < 2; nt++) {
                        mma16816(acc[mt][nt], ah, bh[2 * nt], bh[2 * nt + 1]);
                        mma16816(acc[mt][nt], ah, bl[2 * nt], bl[2 * nt + 1]);
                        mma16816(acc[mt][nt], al, bh[2 * nt], bh[2 * nt + 1]);
                    }
                }
            }

            // C: linearized relu scores; lin folded into each batch store
            float lr;
            {
                float l0 = fmaf(acc[0][0][0], w2a.x, fmaf(acc[0][0][1], w2a.y,
                           fmaf(acc[0][1][0], w2b.x, acc[0][1][1] * w2b.y)));
                float l1 = fmaf(acc[0][0][2], w2a.x, fmaf(acc[0][0][3], w2a.y,
                           fmaf(acc[0][1][2], w2b.x, acc[0][1][3] * w2b.y)));
                float l2 = fmaf(acc[1][0][0], w2a.x, fmaf(acc[1][0][1], w2a.y,
                           fmaf(acc[1][1][0], w2b.x, acc[1][1][1] * w2b.y)));
                float l3 = fmaf(acc[1][0][2], w2a.x, fmaf(acc[1][0][3], w2a.y,
                           fmaf(acc[1][1][2], w2b.x, acc[1][1][3] * w2b.y)));
                lr = quadred4(l0, l1, l2, l3, lane);
            }
            {
                ull ap[8];
#pragma unroll
                for (int mt = 0; mt < 2; mt++)
#pragma unroll
                    for (int nt = 0; nt < 2; nt++) {
                        ap[mt * 4 + nt * 2]     = pack2(acc[mt][nt][0], acc[mt][nt][1]);
                        ap[mt * 4 + nt * 2 + 1] = pack2(acc[mt][nt][2], acc[mt][nt][3]);
                    }
#pragma unroll 4
                for (int b = 0; b < 16; b++) {
                    ull a0 = *(const ull*)&anc[b * 128 + c0];
                    ull a1 = *(const ull*)&anc[b * 128 + c0 + 8];
                    float2 u0 = unpk(fadd2(ap[0], a0));
                    float2 u1 = unpk(fadd2(ap[2], a1));
                    float2 u2 = unpk(fadd2(ap[1], a0));
                    float2 u3 = unpk(fadd2(ap[3], a1));
                    float2 u4 = unpk(fadd2(ap[4], a0));
                    float2 u5 = unpk(fadd2(ap[6], a1));
                    float2 u6 = unpk(fadd2(ap[5], a0));
                    float2 u7 = unpk(fadd2(ap[7], a1));
                    float s0 = fmaf(fabsf(u0.x), w2a.x, fmaf(fabsf(u0.y), w2a.y,
                               fmaf(fabsf(u1.x), w2b.x, fabsf(u1.y) * w2b.y)));
                    float s1 = fmaf(fabsf(u2.x), w2a.x, fmaf(fabsf(u2.y), w2a.y,
                               fmaf(fabsf(u3.x), w2b.x, fabsf(u3.y) * w2b.y)));
                    float s2 = fmaf(fabsf(u4.x), w2a.x, fmaf(fabsf(u4.y), w2a.y,
                               fmaf(fabsf(u5.x), w2b.x, fabsf(u5.y) * w2b.y)));
                    float s3 = fmaf(fabsf(u6.x), w2a.x, fmaf(fabsf(u6.y), w2a.y,
                               fmaf(fabsf(u7.x), w2b.x, fabsf(u7.y) * w2b.y)));
                    sp[spW + b] = quadred4(s0, s1, s2, s3, lane) + lr;
                }
            }
            asm volatile("bar.sync 1, 640;" ::: "memory");   // R1 (only blocking bar)

            // D1: softmax + P-bf16 (lin already folded)
            const int m0 = t * TM;
            {
                const int b = wid, tc = lane;
                float s0 = 0.f, s1 = 0.f;
#pragma unroll
                for (int g = 0; g < 8; g++) {
                    int ba = g * 1216;
                    s0 += sp[ba + tc * 19 + b];
                    s1 += sp[ba + (tc + 32) * 19 + b];
                }
                s0 += linbreg;
                s1 += linbreg;
                if (m0 + tc >= M) s0 = -CUDART_INF_F;
                if (m0 + tc + 32 >= M) s1 = -CUDART_INF_F;
                float tmax = fmaxf(s0, s1);
#pragma unroll
                for (int off = 16; off; off >>= 1)
                    tmax = fmaxf(tmax, __shfl_xor_sync(0xffffffffu, tmax, off));
                float mold = mbp[b], mnew = fmaxf(mold, tmax);
                float p0 = __expf(s0 - mnew), p1 = __expf(s1 - mnew);
                float q0 = __shfl_xor_sync(0xffffffffu, p0, 1);
                float q1 = __shfl_xor_sync(0xffffffffu, p1, 1);
                if (!(tc & 1)) {
                    uint32_t h0 = cvt_bf2(p0, q0);
                    uint32_t h1 = cvt_bf2(p1, q1);
                    float e0 = __uint_as_float(h0 << 16), e1 = __uint_as_float(h0 & 0xffff0000u);
                    float e2 = __uint_as_float(h1 << 16), e3 = __uint_as_float(h1 & 0xffff0000u);
                    uint32_t l0w = cvt_bf2(p0 - e0, q0 - e1);
                    uint32_t l1w = cvt_bf2(p1 - e2, q1 - e3);
                    int r2 = tc >> 1;
                    *(uint32_t*)(smem + SM_PH + b * 144 + 4 * r2)      = h0;
                    *(uint32_t*)(smem + SM_PH + b * 144 + 64 + 4 * r2) = h1;
                    *(uint32_t*)(smem + SM_PL + b * 144 + 4 * r2)      = l0w;
                    *(uint32_t*)(smem + SM_PL + b * 144 + 64 + 4 * r2) = l1w;
                }
                float ps = p0 + p1;
#pragma unroll
                for (int off = 16; off; off >>= 1)
                    ps += __shfl_xor_sync(0xffffffffu, ps, off);
                float scale = __expf(mold - mnew);
                if (tc == 0) { mbp[b] = mnew; lbp[b] = lbp[b] * scale + ps; scsh[b] = scale; }
            }
            asm volatile("bar.arrive 3, 640;" ::: "memory"); // signal P ready (non-blocking)
        }
        if (tid < 16) { g_pm[bxi * 16 + tid] = mbp[tid]; g_pl[bxi * 16 + tid] = lbp[tid]; }
    } else {
        // ===================== LOADER WARPS (4) =====================
        const int lw = tid - 512;                 // 0..127
        const int d0 = (wid - 16) * 32;
        const uint32_t pA = smb + SM_PH + (uint32_t)(((lane & 7) + 8 * ((lane >> 3) & 1)) * 144
                             + 16 * (lane >> 4));
        float accV[4][4];
#pragma unroll
        for (int g = 0; g < 4; g++)
#pragma unroll
            for (int e = 0; e < 4; e++) accV[g][e] = 0.f;

        LDST_X(bxi * TM, 0u)                              // X(t0) -> buf0
        if (bxi + NB < nTiles) LDST_X((bxi + NB) * TM, 32768u)  // X(t1) -> buf1
        __syncthreads();

        int k = 0;
        for (int t = bxi; t < nTiles; t += NB, k++) {
            const uint32_t xb = (uint32_t)((k & 1) * 32768);
            asm volatile("bar.sync 1, 640;" ::: "memory");   // R1
            asm volatile("bar.sync 3, 640;" ::: "memory");   // wait P(t)

            // D2: V += P(t) * X(t); P fragments hoisted
            {
                float sc0 = scsh[lane >> 2], sc1 = scsh[(lane >> 2) + 8];
                uint32_t ah[4][4], al[4][4];
#pragma unroll
                for (int kt = 0; kt < 4; kt++) {
                    ldsm4(ah[kt], pA + 32 * kt);
                    ldsm4(al[kt], pA + 2304 + 32 * kt);
                }
#pragma unroll
                for (int g = 0; g < 4; g++) {
                    accV[g][0] *= sc0; accV[g][1] *= sc0;
                    accV[g][2] *= sc1; accV[g][3] *= sc1;
                    uint32_t bh[8], bl[8];
                    uint32_t x0 = smb + SM_X + xb + swz(lane, d0 + 8 * g, 8);
                    uint32_t x1 = smb + SM_X + xb + swz(32 + lane, d0 + 8 * g, 8);
                    ldsm4t(bh, x0); ldsm4t(bh + 4, x1);
                    ldsm4t(bl, x0 + 16384); ldsm4t(bl + 4, x1 + 16384);
#pragma unroll
                    for (int kt = 0; kt < 4; kt++) {
                        mma16816(accV[g], ah[kt], bh[2 * kt], bh[2 * kt + 1]);
                        mma16816(accV[g], ah[kt], bl[2 * kt], bl[2 * kt + 1]);
                        mma16816(accV[g], al[kt], bh[2 * kt], bh[2 * kt + 1]);
                    }
                }
            }
            asm volatile("bar.sync 4, 128;" ::: "memory");   // X(t) fully consumed
            if (t + 2 * NB < nTiles) LDST_X((t + 2 * NB) * TM, xb)
        }
#pragma unroll
        for (int g = 0; g < 4; g++) {
            int b = lane >> 2, d = d0 + 8 * g + 2 * (lane & 3);
            *(float2*)&g_pv[bxi * 2048 + b * 128 + d]       = make_float2(accV[g][0], accV[g][1]);
            *(float2*)&g_pv[bxi * 2048 + (b + 8) * 128 + d] = make_float2(accV[g][2], accV[g][3]);
        }
    }
    __syncthreads();
    __threadfence();

    int* flg = (int*)(smem + SM_FLG);
    if (tid == 0) flg[0] = (atomicAdd(&g_cnt, 1) == NB - 1) ? 1 : 0;
    __syncthreads();
    if (flg[0]) {
        float* fsh = (float*)(smem + SM_FSH);
        if (tid < 16) {
            float Mx = -CUDART_INF_F;
            for (int j = 0; j < NB; j++) Mx = fmaxf(Mx, g_pm[j * 16 + tid]);
            mbp[tid] = Mx;
        }
        __syncthreads();
        for (int i = tid; i < NB * 16; i += NTHR)
            fsh[i] = __expf(g_pm[i] - mbp[i & 15]);
        __syncthreads();
        if (tid < 16) {
            float L = 0.f;
            for (int j = 0; j < NB; j++) L = fmaf(g_pl[j * 16 + tid], fsh[j * 16 + tid], L);
            lbp[tid] = L;
        }
        __syncthreads();
        if (tid < 512) {
            int b = tid >> 5, d4 = (tid & 31) * 4;
            float4 V = make_float4(0.f, 0.f, 0.f, 0.f);
#pragma unroll 4
            for (int j = 0; j < NB; j++) {
                float f = fsh[j * 16 + b];
                float4 pv = *(const float4*)&g_pv[j * 2048 + b * 128 + d4];
                V.x = fmaf(pv.x, f, V.x); V.y = fmaf(pv.y, f, V.y);
                V.z = fmaf(pv.z, f, V.z); V.w = fmaf(pv.w, f, V.w);
            }
            float inv = 1.f / lbp[b];
            *(float4*)&out[b * 128 + d4] =
                make_float4(V.x * inv, V.y * inv, V.z * inv, V.w * inv);
        }
        if (tid == 0) g_cnt = 0;
    }
}

extern "C" void kernel_launch(void* const* d_in, const int* in_sizes, int n_in,
                              void* d_out, int out_size) {
    const float* xxa = (const float*)d_in[0];
    const float* X   = (const float*)d_in[1];
    const float* W1  = (const float*)d_in[3];
    const float* W2  = (const float*)d_in[4];
    float* out = (float*)d_out;
    int M = in_sizes[1] / DF;
    int nTiles = (M + TM - 1) / TM;
    cudaFuncSetAttribute(main_kernel, cudaFuncAttributeMaxDynamicSharedMemorySize, SMEM_TOTAL);
    prep_kernel<<<144, 512>>>(xxa, W1);
    main_kernel<<<NB, NTHR, SMEM_TOTAL>>>(X, W2, out, M, nTiles);
}

// round 17
// speedup vs baseline: 1.0448x; 1.0448x over previous
#include <cuda_runtime.h>
#include <cuda_bf16.h>
#include <math_constants.h>
#include <cstdint>

#define NB 148
#define TM 64
#define DF 128
#define BATCH 16
#define NTHR 640

#define SM_WH 0
#define SM_WL 32768
#define SM_X  65536          // 2 buffers x (XH 16K + XL 16K)
#define SM_PH 131072
#define SM_PL 133376
#define SM_SPART 135680      // 2 x [8 nga][64 r][19]
#define SM_ANC 213504
#define SM_LB 221696
#define SM_FLG 221760
#define SMEM_TOTAL 221824
#define SM_FSH SM_SPART

typedef unsigned long long ull;

__device__ __forceinline__ uint32_t smem_u32(const void* p) {
    uint32_t a;
    asm("{ .reg .u64 t; cvta.to.shared.u64 t, %1; cvt.u32.u64 %0, t; }" : "=r"(a) : "l"(p));
    return a;
}
__device__ __forceinline__ uint32_t cvt_bf2(float lo, float hi) {
    uint32_t r; asm("cvt.rn.bf16x2.f32 %0, %1, %2;" : "=r"(r) : "f"(hi), "f"(lo)); return r;
}
__device__ __forceinline__ ull fadd2(ull a, ull b) {
    ull d; asm("add.rn.f32x2 %0, %1, %2;" : "=l"(d) : "l"(a), "l"(b)); return d;
}
__device__ __forceinline__ ull pack2(float a, float b) {
    ull d; asm("mov.b64 %0, {%1, %2};" : "=l"(d) : "f"(a), "f"(b)); return d;
}
__device__ __forceinline__ float2 unpk(ull v) {
    float2 r; asm("mov.b64 {%0, %1}, %2;" : "=f"(r.x), "=f"(r.y) : "l"(v)); return r;
}
__device__ __forceinline__ void ldsm4(uint32_t* d, uint32_t a) {
    asm volatile("ldmatrix.sync.aligned.m8n8.x4.shared.b16 {%0,%1,%2,%3}, [%4];"
        : "=r"(d[0]), "=r"(d[1]), "=r"(d[2]), "=r"(d[3]) : "r"(a));
}
__device__ __forceinline__ void ldsm4t(uint32_t* d, uint32_t a) {
    asm volatile("ldmatrix.sync.aligned.m8n8.x4.trans.shared.b16 {%0,%1,%2,%3}, [%4];"
        : "=r"(d[0]), "=r"(d[1]), "=r"(d[2]), "=r"(d[3]) : "r"(a));
}
__device__ __forceinline__ void mma16816(float* c, const uint32_t* a, uint32_t b0, uint32_t b1) {
    asm volatile("mma.sync.aligned.m16n8k16.row.col.f32.bf16.bf16.f32 "
        "{%0,%1,%2,%3}, {%4,%5,%6,%7}, {%8,%9}, {%0,%1,%2,%3};"
        : "+f"(c[0]), "+f"(c[1]), "+f"(c[2]), "+f"(c[3])
        : "r"(a[0]), "r"(a[1]), "r"(a[2]), "r"(a[3]), "r"(b0), "r"(b1));
}
__device__ __forceinline__ uint32_t swz(int row, int col, int AC) {
    uint32_t o = (uint32_t)(((row >> 3) + (col >> 6) * AC) * 1024 + (row & 7) * 128 + (col & 63) * 2);
    return o ^ ((o >> 3) & 0x70);
}
__device__ __forceinline__ float quadred4(float s0, float s1, float s2, float s3, int lane) {
    float u = (lane & 1) ? s0 : s1;
    u = __shfl_xor_sync(0xffffffffu, u, 1);
    float A = (lane & 1) ? (s1 + u) : (s0 + u);
    float v = (lane & 1) ? s2 : s3;
    v = __shfl_xor_sync(0xffffffffu, v, 1);
    float Bv = (lane & 1) ? (s3 + v) : (s2 + v);
    float w = (lane & 2) ? A : Bv;
    w = __shfl_xor_sync(0xffffffffu, w, 2);
    return ((lane & 2) ? Bv : A) + w;
}

__device__ uint32_t g_Wh[8192];
__device__ uint32_t g_Wl[8192];
__device__ float g_anchor[BATCH * 128];
__device__ float g_pl[NB * BATCH];
__device__ float g_pv[NB * BATCH * DF];
__device__ int g_cnt = 0;

__global__ __launch_bounds__(512)
void prep_kernel(const float* __restrict__ xxa, const float* __restrict__ W1) {
    int blk = blockIdx.x;
    if (blk < 16) {
        int idx = blk * 512 + threadIdx.x;
        int o = idx >> 6, k0 = (idx & 63) * 2;
        float w0 = W1[o * 256 + 128 + k0], w1 = W1[o * 256 + 128 + k0 + 1];
        uint32_t h = cvt_bf2(w0, w1);
        float h0 = __uint_as_float(h << 16), h1 = __uint_as_float(h & 0xffff0000u);
        uint32_t sw = swz(o, k0, 16) >> 2;
        g_Wh[sw] = h;
        g_Wl[sw] = cvt_bf2(w0 - h0, w1 - h1);
    } else {
        int gw = (blk - 16) * 16 + (threadIdx.x >> 5);
        int lane = threadIdx.x & 31;
        int b = gw >> 7, o = gw & 127;
        float4 xa = *(const float4*)&xxa[b * 128 + lane * 4];
        float4 wv = *(const float4*)&W1[o * 256 + lane * 4];
        float s = xa.x * wv.x;
        s = fmaf(xa.y, wv.y, s); s = fmaf(xa.z, wv.z, s); s = fmaf(xa.w, wv.w, s);
#pragma unroll
        for (int off = 16; off; off >>= 1) s += __shfl_xor_sync(0xffffffffu, s, off);
        if (lane == 0) g_anchor[b * 128 + o] = s;
    }
}

#define LDST_X(mm, bo) {                                                    \
    _Pragma("unroll 4")                                                     \
    for (int jj = 0; jj < 16; jj++) {                                       \
        int idx = lw + 128 * jj;                                            \
        int r = idx >> 5, c4 = (idx & 31) * 4;                              \
        float4 v = *(const float4*)&X[(size_t)min((mm) + r, M - 1) * DF + c4]; \
        uint32_t h0 = cvt_bf2(v.x, v.y), h1 = cvt_bf2(v.z, v.w);            \
        float f0 = __uint_as_float(h0 << 16), f1 = __uint_as_float(h0 & 0xffff0000u); \
        float f2 = __uint_as_float(h1 << 16), f3 = __uint_as_float(h1 & 0xffff0000u); \
        uint32_t l0 = cvt_bf2(v.x - f0, v.y - f1);                          \
        uint32_t l1 = cvt_bf2(v.z - f2, v.w - f3);                          \
        uint32_t so = swz(r, c4, 8) + (bo);                                 \
        *(ull*)(smem + SM_X + so) = (ull)h0 | ((ull)h1 << 32);              \
        *(ull*)(smem + SM_X + 16384 + so) = (ull)l0 | ((ull)l1 << 32);      \
    } }

__global__ __launch_bounds__(NTHR, 1)
void main_kernel(const float* __restrict__ X, const float* __restrict__ W2,
                 float* __restrict__ out, int M, int nTiles) {
    extern __shared__ char smem[];
    const uint32_t smb = smem_u32(smem);
    float* spart = (float*)(smem + SM_SPART);
    float* anc   = (float*)(smem + SM_ANC);
    float* lbp   = (float*)(smem + SM_LB);

    const int tid = threadIdx.x, bxi = blockIdx.x;
    const int wid = tid >> 5, lane = tid & 31;

    {
        const float4* wh = (const float4*)g_Wh;
        const float4* wl = (const float4*)g_Wl;
        float4* dh = (float4*)(smem + SM_WH);
        float4* dl = (float4*)(smem + SM_WL);
        for (int i = tid; i < 2048; i += NTHR) { dh[i] = wh[i]; dl[i] = wl[i]; }
        for (int i = tid; i < BATCH * 128; i += NTHR) anc[i] = g_anchor[i];
    }

    if (wid < 16) {
        // ===================== COMPUTE WARPS =====================
        const int mga = wid >> 3, nga = wid & 7;
        const int lgrp = lane >> 3;
        const int aRow0 = mga * 32 + (lgrp & 1) * 8 + (lane & 7);
        const uint32_t aB0 = smb + SM_X + ((uint32_t)(aRow0 >> 3) << 10) + ((uint32_t)(aRow0 & 7) << 7);
        const uint32_t cxa = ((uint32_t)((lgrp >> 1) * 16)) ^ ((uint32_t)(aRow0 & 7) << 4);
        const int bRow = nga * 16 + (lgrp >> 1) * 8 + (lane & 7);
        const uint32_t bB = smb + SM_WH + ((uint32_t)(bRow >> 3) << 10) + ((uint32_t)(bRow & 7) << 7);
        const uint32_t cxb = ((uint32_t)((lgrp & 1) * 16)) ^ ((uint32_t)(bRow & 7) << 4);
        const int c0 = nga * 16 + (lane & 3) * 2;
        const float2 w2a = make_float2(0.5f * W2[c0], 0.5f * W2[c0 + 1]);
        const float2 w2b = make_float2(0.5f * W2[c0 + 8], 0.5f * W2[c0 + 9]);
        const int spW = nga * 1216 + (mga * 32 + (lane >> 2) + 8 * (lane & 3)) * 19;

        float linbreg;
        {
            float4 a4 = *(const float4*)&g_anchor[wid * 128 + lane * 4];
            float4 w4 = *(const float4*)&W2[lane * 4];
            float d = a4.x * w4.x;
            d = fmaf(a4.y, w4.y, d); d = fmaf(a4.z, w4.z, d); d = fmaf(a4.w, w4.w, d);
#pragma unroll
            for (int off = 16; off; off >>= 1) d += __shfl_xor_sync(0xffffffffu, d, off);
            linbreg = 0.5f * d;
        }
        float lacc = 0.f;                 // per-lane softmax-denominator partial
        __syncthreads();                  // initial X tiles stored by loaders

        int k = 0;
        for (int t = bxi; t < nTiles; t += NB, k++) {
            const uint32_t xb = (uint32_t)((k & 1) * 32768);
            float* sp = spart + (k & 1) * 9728;

            // B: NP GEMM
            float acc[2][2][4];
#pragma unroll
            for (int mt = 0; mt < 2; mt++)
#pragma unroll
                for (int nt = 0; nt < 2; nt++)
#pragma unroll
                    for (int e = 0; e < 4; e++) acc[mt][nt][e] = 0.f;
#pragma unroll
            for (int ks = 0; ks < 8; ks++) {
                uint32_t kb = (uint32_t)((ks & 3) * 32);
                uint32_t aAddr = aB0 + xb + (uint32_t)((ks >> 2) * 8192)  + (kb ^ cxa);
                uint32_t bAddr = bB  + (uint32_t)((ks >> 2) * 16384) + (kb ^ cxb);
                uint32_t ah0[4], ah1[4], al0[4], al1[4], bh[4], bl[4];
                ldsm4(ah0, aAddr);
                ldsm4(ah1, aAddr + 2048);
                ldsm4(al0, aAddr + 16384);
                ldsm4(al1, aAddr + 18432);
                ldsm4(bh, bAddr);
                ldsm4(bl, bAddr + 32768);
#pragma unroll
                for (int mt = 0; mt < 2; mt++) {
                    const uint32_t* ah = mt ? ah1 : ah0;
                    const uint32_t* al = mt ? al1 : al0;
#pragma unroll
                    for (int nt = 0; nt < 2; nt++) {
                        mma16816(acc[mt][nt], ah, bh[2 * nt], bh[2 * nt + 1]);
                        mma16816(acc[mt][nt], ah, bl[2 * nt], bl[2 * nt + 1]);
                        mma16816(acc[mt][nt], al, bh[2 * nt], bh[2 * nt + 1]);
                    }
                }
            }

            // C: linearized relu scores; lin folded into batch stores
            float lr;
            {
                float l0 = fmaf(acc[0][0][0], w2a.x, fmaf(acc[0][0][1], w2a.y,
                           fmaf(acc[0][1][0], w2b.x, acc[0][1][1] * w2b.y)));
                float l1 = fmaf(acc[0][0][2], w2a.x, fmaf(acc[0][0][3], w2a.y,
                           fmaf(acc[0][1][2], w2b.x, acc[0][1][3] * w2b.y)));
                float l2 = fmaf(acc[1][0][0], w2a.x, fmaf(acc[1][0][1], w2a.y,
                           fmaf(acc[1][1][0], w2b.x, acc[1][1][1] * w2b.y)));
                float l3 = fmaf(acc[1][0][2], w2a.x, fmaf(acc[1][0][3], w2a.y,
                           fmaf(acc[1][1][2], w2b.x, acc[1][1][3] * w2b.y)));
                lr = quadred4(l0, l1, l2, l3, lane);
            }
            {
                ull ap[8];
#pragma unroll
                for (int mt = 0; mt < 2; mt++)
#pragma unroll
                    for (int nt = 0; nt < 2; nt++) {
                        ap[mt * 4 + nt * 2]     = pack2(acc[mt][nt][0], acc[mt][nt][1]);
                        ap[mt * 4 + nt * 2 + 1] = pack2(acc[mt][nt][2], acc[mt][nt][3]);
                    }
#pragma unroll 4
                for (int b = 0; b < 16; b++) {
                    ull a0 = *(const ull*)&anc[b * 128 + c0];
                    ull a1 = *(const ull*)&anc[b * 128 + c0 + 8];
                    float2 u0 = unpk(fadd2(ap[0], a0));
                    float2 u1 = unpk(fadd2(ap[2], a1));
                    float2 u2 = unpk(fadd2(ap[1], a0));
                    float2 u3 = unpk(fadd2(ap[3], a1));
                    float2 u4 = unpk(fadd2(ap[4], a0));
                    float2 u5 = unpk(fadd2(ap[6], a1));
                    float2 u6 = unpk(fadd2(ap[5], a0));
                    float2 u7 = unpk(fadd2(ap[7], a1));
                    float s0 = fmaf(fabsf(u0.x), w2a.x, fmaf(fabsf(u0.y), w2a.y,
                               fmaf(fabsf(u1.x), w2b.x, fabsf(u1.y) * w2b.y)));
                    float s1 = fmaf(fabsf(u2.x), w2a.x, fmaf(fabsf(u2.y), w2a.y,
                               fmaf(fabsf(u3.x), w2b.x, fabsf(u3.y) * w2b.y)));
                    float s2 = fmaf(fabsf(u4.x), w2a.x, fmaf(fabsf(u4.y), w2a.y,
                               fmaf(fabsf(u5.x), w2b.x, fabsf(u5.y) * w2b.y)));
                    float s3 = fmaf(fabsf(u6.x), w2a.x, fmaf(fabsf(u6.y), w2a.y,
                               fmaf(fabsf(u7.x), w2b.x, fabsf(u7.y) * w2b.y)));
                    sp[spW + b] = quadred4(s0, s1, s2, s3, lane) + lr;
                }
            }
            asm volatile("bar.sync 1, 640;" ::: "memory");   // R1

            // D1 (no max shift): p = exp(s), lacc += p, P -> bf16 hi/lo
            const int m0 = t * TM;
            {
                const int b = wid, tc = lane;
                float s0 = 0.f, s1 = 0.f;
#pragma unroll
                for (int g = 0; g < 8; g++) {
                    int ba = g * 1216;
                    s0 += sp[ba + tc * 19 + b];
                    s1 += sp[ba + (tc + 32) * 19 + b];
                }
                s0 += linbreg;
                s1 += linbreg;
                if (m0 + tc >= M) s0 = -CUDART_INF_F;
                if (m0 + tc + 32 >= M) s1 = -CUDART_INF_F;
                float p0 = __expf(s0), p1 = __expf(s1);
                lacc += p0 + p1;
                float q0 = __shfl_xor_sync(0xffffffffu, p0, 1);
                float q1 = __shfl_xor_sync(0xffffffffu, p1, 1);
                if (!(tc & 1)) {
                    uint32_t h0 = cvt_bf2(p0, q0);
                    uint32_t h1 = cvt_bf2(p1, q1);
                    float e0 = __uint_as_float(h0 << 16), e1 = __uint_as_float(h0 & 0xffff0000u);
                    float e2 = __uint_as_float(h1 << 16), e3 = __uint_as_float(h1 & 0xffff0000u);
                    uint32_t l0w = cvt_bf2(p0 - e0, q0 - e1);
                    uint32_t l1w = cvt_bf2(p1 - e2, q1 - e3);
                    int r2 = tc >> 1;
                    *(uint32_t*)(smem + SM_PH + b * 144 + 4 * r2)      = h0;
                    *(uint32_t*)(smem + SM_PH + b * 144 + 64 + 4 * r2) = h1;
                    *(uint32_t*)(smem + SM_PL + b * 144 + 4 * r2)      = l0w;
                    *(uint32_t*)(smem + SM_PL + b * 144 + 64 + 4 * r2) = l1w;
                }
            }
            asm volatile("bar.arrive 3, 640;" ::: "memory"); // P ready (non-blocking)
        }
        // final denominator reduce (once)
#pragma unroll
        for (int off = 16; off; off >>= 1)
            lacc += __shfl_xor_sync(0xffffffffu, lacc, off);
        if (lane == 0) g_pl[bxi * 16 + wid] = lacc;
    } else {
        // ===================== LOADER WARPS (4) =====================
        const int lw = tid - 512;
        const int d0 = (wid - 16) * 32;
        const uint32_t pA = smb + SM_PH + (uint32_t)(((lane & 7) + 8 * ((lane >> 3) & 1)) * 144
                             + 16 * (lane >> 4));
        float accV[4][4];
#pragma unroll
        for (int g = 0; g < 4; g++)
#pragma unroll
            for (int e = 0; e < 4; e++) accV[g][e] = 0.f;

        LDST_X(bxi * TM, 0u)
        if (bxi + NB < nTiles) LDST_X((bxi + NB) * TM, 32768u)
        __syncthreads();

        int k = 0;
        for (int t = bxi; t < nTiles; t += NB, k++) {
            const uint32_t xb = (uint32_t)((k & 1) * 32768);
            asm volatile("bar.sync 1, 640;" ::: "memory");   // R1
            asm volatile("bar.sync 3, 640;" ::: "memory");   // wait P(t)

            // D2: V += P(t) * X(t); no rescale (m fixed)
            {
                uint32_t ah[4][4], al[4][4];
#pragma unroll
                for (int kt = 0; kt < 4; kt++) {
                    ldsm4(ah[kt], pA + 32 * kt);
                    ldsm4(al[kt], pA + 2304 + 32 * kt);
                }
#pragma unroll
                for (int g = 0; g < 4; g++) {
                    uint32_t bh[8], bl[8];
                    uint32_t x0 = smb + SM_X + xb + swz(lane, d0 + 8 * g, 8);
                    uint32_t x1 = smb + SM_X + xb + swz(32 + lane, d0 + 8 * g, 8);
                    ldsm4t(bh, x0); ldsm4t(bh + 4, x1);
                    ldsm4t(bl, x0 + 16384); ldsm4t(bl + 4, x1 + 16384);
#pragma unroll
                    for (int kt = 0; kt < 4; kt++) {
                        mma16816(accV[g], ah[kt], bh[2 * kt], bh[2 * kt + 1]);
                        mma16816(accV[g], ah[kt], bl[2 * kt], bl[2 * kt + 1]);
                        mma16816(accV[g], al[kt], bh[2 * kt], bh[2 * kt + 1]);
                    }
                }
            }
            asm volatile("bar.sync 4, 128;" ::: "memory");   // X(t) consumed
            if (t + 2 * NB < nTiles) LDST_X((t + 2 * NB) * TM, xb)
        }
#pragma unroll
        for (int g = 0; g < 4; g++) {
            int b = lane >> 2, d = d0 + 8 * g + 2 * (lane & 3);
            *(float2*)&g_pv[bxi * 2048 + b * 128 + d]       = make_float2(accV[g][0], accV[g][1]);
            *(float2*)&g_pv[bxi * 2048 + (b + 8) * 128 + d] = make_float2(accV[g][2], accV[g][3]);
        }
    }
    __syncthreads();
    __threadfence();

    int* flg = (int*)(smem + SM_FLG);
    if (tid == 0) flg[0] = (atomicAdd(&g_cnt, 1) == NB - 1) ? 1 : 0;
    __syncthreads();
    if (flg[0]) {
        if (tid < 16) {
            float L = 0.f;
            for (int j = 0; j < NB; j++) L += g_pl[j * 16 + tid];
            lbp[tid] = L;
        }
        __syncthreads();
        if (tid < 512) {
            int b = tid >> 5, d4 = (tid & 31) * 4;
            float4 V = make_float4(0.f, 0.f, 0.f, 0.f);
#pragma unroll 4
            for (int j = 0; j < NB; j++) {
                float4 pv = *(const float4*)&g_pv[j * 2048 + b * 128 + d4];
                V.x += pv.x; V.y += pv.y; V.z += pv.z; V.w += pv.w;
            }
            float inv = 1.f / lbp[b];
            *(float4*)&out[b * 128 + d4] =
                make_float4(V.x * inv, V.y * inv, V.z * inv, V.w * inv);
        }
        if (tid == 0) g_cnt = 0;
    }
}

extern "C" void kernel_launch(void* const* d_in, const int* in_sizes, int n_in,
                              void* d_out, int out_size) {
    const float* xxa = (const float*)d_in[0];
    const float* X   = (const float*)d_in[1];
    const float* W1  = (const float*)d_in[3];
    const float* W2  = (const float*)d_in[4];
    float* out = (float*)d_out;
    int M = in_sizes[1] / DF;
    int nTiles = (M + TM - 1) / TM;
    cudaFuncSetAttribute(main_kernel, cudaFuncAttributeMaxDynamicSharedMemorySize, SMEM_TOTAL);
    prep_kernel<<<144, 512>>>(xxa, W1);
    main_kernel<<<NB, NTHR, SMEM_TOTAL>>>(X, W2, out, M, nTiles);
}